// round 12
// baseline (speedup 1.0000x reference)
#include <cuda_runtime.h>
#include <cuda_fp16.h>
#include <cstdint>
#include <cstddef>

// ---------------- problem constants ----------------
#define BATCH 16384
#define JNT   17
#define FIN   256
#define FOUT  256
#define MROWS (BATCH * JNT)          // 278528 = 2176 * 128
#define PROW  384                    // uint32 (fp16-pairs) per z row

// GEMM tiling: CTA 128x128, 8 warps of 64x32, BK=64; A 3-stage, B 2-stage
#define BM 128
#define BN 128
#define NKIT 12
#define ASTRIDE 40
#define BSTRIDE 40
#define ASZW (BM * ASTRIDE)          // 5120 uint32 per A stage
#define BSZW (BN * BSTRIDE)          // 5120 uint32 per B stage
#define B_OFF (3 * ASZW)
#define SMEM_BYTES ((3 * ASZW + 2 * BSZW) * 4)   // 102400 -> 2 CTAs/SM

#define NAGG  (BATCH / 4)            // 4096 agg blocks
#define NGEMM (2 * MROWS / BM)       // 4352 gemm blocks
#define HEAD  512                    // leading all-agg bids

// ---------------- device scratch ----------------
__device__ uint32_t g_z[(size_t)MROWS * PROW];       // z fp16 pairs (~428MB)
__device__ uint32_t g_wb[(size_t)NKIT * 256 * 32];   // Wcat prepacked fp16
__device__ int g_flag[NAGG];                         // z-ready flags

// ---------------- helpers ----------------
__device__ __forceinline__ uint32_t smem_u32(const void* p) {
    uint32_t a;
    asm("{ .reg .u64 t; cvta.to.shared.u64 t, %1; cvt.u32.u64 %0, t; }" : "=r"(a) : "l"(p));
    return a;
}
__device__ __forceinline__ void cp16(uint32_t dst, const void* src) {
    asm volatile("cp.async.cg.shared.global [%0], [%1], 16;" :: "r"(dst), "l"(src));
}
#define CP_COMMIT() asm volatile("cp.async.commit_group;" ::: "memory")
#define CP_WAIT1()  asm volatile("cp.async.wait_group 1;" ::: "memory")

__device__ __forceinline__ void mma_f16(float* d, uint32_t a0, uint32_t a1,
                                        uint32_t a2, uint32_t a3,
                                        uint32_t b0, uint32_t b1) {
    asm volatile(
        "mma.sync.aligned.m16n8k16.row.col.f32.f16.f16.f32 "
        "{%0,%1,%2,%3}, {%4,%5,%6,%7}, {%8,%9}, {%0,%1,%2,%3};"
        : "+f"(d[0]), "+f"(d[1]), "+f"(d[2]), "+f"(d[3])
        : "r"(a0), "r"(a1), "r"(a2), "r"(a3), "r"(b0), "r"(b1));
}
__device__ __forceinline__ uint32_t pack2(float lo, float hi) {
    __half2 h = __floats2half2_rn(lo, hi);
    return *reinterpret_cast<uint32_t*>(&h);
}
__device__ __forceinline__ void flag_release(int* p) {
    asm volatile("st.release.gpu.s32 [%0], %1;" :: "l"(p), "r"(1) : "memory");
}
__device__ __forceinline__ int flag_acquire(const int* p) {
    int v;
    asm volatile("ld.acquire.gpu.s32 %0, [%1];" : "=r"(v) : "l"(p) : "memory");
    return v;
}

// pair-interleave: within each 8-pair group, slot (2m, 2m+1) holds pairs (m, m+4).

// ---------------- kernel 0: flag reset + W prepack ----------------
__global__ void __launch_bounds__(256) prep_kernel(const float* __restrict__ W) {
    int idx = blockIdx.x * 256 + threadIdx.x;     // 384*256 = 98304
    if (idx < NAGG) g_flag[idx] = 0;
    int s = idx & 31;
    int n = (idx >> 5) & 255;
    int t = idx >> 13;
    int sp = s & 7;
    int q = (sp >> 1) + ((sp & 1) << 2);          // inverse interleave
    int P = t * 32 + (s >> 3) * 8 + q;
    int k0 = 2 * P;
    g_wb[idx] = pack2(W[k0 * FOUT + n], W[(k0 + 1) * FOUT + n]);
}

// ---------------- gemm-role loads ----------------
__device__ __forceinline__ void load_a(uint32_t sb, int t, int s, int tid, size_t mbase) {
    const uint32_t* za = g_z + mbase * PROW + t * 32;
    uint32_t as = sb + (uint32_t)s * ASZW * 4;
    #pragma unroll
    for (int qq = 0; qq < 4; qq++) {
        int id = tid + qq * 256;                  // 1024 chunks
        int row = id >> 3, ck = id & 7;
        cp16(as + (row * ASTRIDE + ck * 4) * 4, za + (size_t)row * PROW + ck * 4);
    }
}
__device__ __forceinline__ void load_b(uint32_t sb, int t, int s, int tid, int nbase) {
    const uint32_t* wb = g_wb + ((size_t)t * 256 + nbase) * 32;
    uint32_t bs = sb + ((uint32_t)(B_OFF + s * BSZW)) * 4;
    #pragma unroll
    for (int qq = 0; qq < 4; qq++) {
        int id = tid + qq * 256;
        int row = id >> 3, ck = id & 7;
        cp16(bs + (row * BSTRIDE + ck * 4) * 4, wb + id * 4);
    }
}

// ---------------- fused kernel, interleaved roles ----------------
// bid < 512            : agg idx = bid
// 512 <= bid < 7680    : even offset -> agg idx 512 + off/2 ; odd -> gemm idx off/2
// bid >= 7680          : gemm idx = 3584 + (bid - 7680)
__global__ void __launch_bounds__(256, 2)
fused_kernel(const float* __restrict__ x, const float* __restrict__ adj,
             const float* __restrict__ bias, float* __restrict__ out) {
    extern __shared__ uint32_t sm[];
    const int tid = threadIdx.x;
    const int bid = blockIdx.x;

    int is_agg, idx;
    if (bid < HEAD) { is_agg = 1; idx = bid; }
    else if (bid < HEAD + 2 * (NAGG - HEAD)) {
        int off = bid - HEAD;
        is_agg = ((off & 1) == 0);
        idx = is_agg ? (HEAD + (off >> 1)) : (off >> 1);
    } else { is_agg = 0; idx = (NAGG - HEAD) + (bid - HEAD - 2 * (NAGG - HEAD)); }

    if (is_agg) {
        // =============== agg role: 4 batches -> z, release flag ===============
        float* sx   = (float*)sm;                 // 4*17*256 floats
        float* sadj = sx + 4 * JNT * FIN;         // 289 floats
        const int b0 = idx * 4;

        const float4* xs = (const float4*)(x + (size_t)b0 * JNT * FIN);
        float4* sd = (float4*)sx;
        #pragma unroll
        for (int t = tid; t < 4 * JNT * FIN / 4; t += 256) sd[t] = xs[t];
        for (int t = tid; t < JNT * JNT; t += 256) sadj[t] = adj[t];
        __syncthreads();

        const int sub = tid >> 6;
        const int u = tid & 63;
        const int G = u >> 2, m = u & 3;
        const int f0 = G * 16 + m * 2;
        const float* xb = sx + sub * JNT * FIN;

        float2 xlo[JNT], xhi[JNT];
        #pragma unroll
        for (int j = 0; j < JNT; j++) {
            xlo[j] = *(const float2*)(xb + j * FIN + f0);
            xhi[j] = *(const float2*)(xb + j * FIN + f0 + 8);
        }

        const int slot = G * 8 + 2 * m;
        uint32_t* zr = g_z + (size_t)(b0 + sub) * JNT * PROW;

        #pragma unroll
        for (int i = 0; i < JNT; i++) {
            float ad = sadj[i * JNT + i];
            float2 d_lo = make_float2(ad * xlo[i].x, ad * xlo[i].y);
            float2 d_hi = make_float2(ad * xhi[i].x, ad * xhi[i].y);
            float2 s1l = make_float2(0.f, 0.f), s1h = make_float2(0.f, 0.f);
            float2 s2l = make_float2(0.f, 0.f), s2h = make_float2(0.f, 0.f);
            #pragma unroll
            for (int j = 0; j < JNT; j++) {
                float a = sadj[i * JNT + j];
                if (j > i) {
                    s1l.x += a * xlo[j].x; s1l.y += a * xlo[j].y;
                    s1h.x += a * xhi[j].x; s1h.y += a * xhi[j].y;
                }
                if (j < i) {
                    s2l.x += a * xlo[j].x; s2l.y += a * xlo[j].y;
                    s2h.x += a * xhi[j].x; s2h.y += a * xhi[j].y;
                }
            }
            uint32_t* zi = zr + i * PROW;
            *(uint2*)(zi + slot)       = make_uint2(pack2(d_lo.x, d_lo.y), pack2(d_hi.x, d_hi.y));
            *(uint2*)(zi + 128 + slot) = make_uint2(pack2(s1l.x, s1l.y), pack2(s1h.x, s1h.y));
            *(uint2*)(zi + 256 + slot) = make_uint2(pack2(s2l.x, s2l.y), pack2(s2h.x, s2h.y));
        }

        __threadfence();
        __syncthreads();
        if (tid == 0) flag_release(&g_flag[idx]);
        return;
    }

    // =============== gemm role: out = z @ Wcat + bias ===============
    const int g = idx;
    const int nbase = (g & 1) * BN;               // N-halves adjacent -> A hits L2
    const size_t mbase = (size_t)(g >> 1) * BM;
    const uint32_t sb = smem_u32(sm);
    const int wid = tid >> 5;
    const int lane = tid & 31;
    const int warp_m = wid & 1;                   // 2 x 64 = 128 M
    const int warp_n = wid >> 1;                  // 4 x 32 = 128 N
    const int r = lane >> 2;
    const int c = lane & 3;

    // wait for z of batches [mbase/17, (mbase+127)/17]
    if (tid == 0) {
        int f0 = (int)(mbase / JNT) >> 2;
        int f1 = (int)((mbase + BM - 1) / JNT) >> 2;
        for (int f = f0; f <= f1; f++)
            while (flag_acquire(&g_flag[f]) == 0) __nanosleep(64);
    }
    __syncthreads();

    float acc[64];
    #pragma unroll
    for (int i = 0; i < 64; i++) acc[i] = 0.0f;

    // prologue: group {A0,B0}, group {A1}
    load_a(sb, 0, 0, tid, mbase);
    load_b(sb, 0, 0, tid, nbase);
    CP_COMMIT();
    load_a(sb, 1, 1, tid, mbase);
    CP_COMMIT();

    int abuf = 0;                                 // t % 3
    for (int t = 0; t < NKIT; t++) {
        CP_WAIT1();                               // A(t), B(t) landed
        __syncthreads();                          // visible; iter t-1 reads done

        if (t + 1 < NKIT) load_b(sb, t + 1, (t + 1) & 1, tid, nbase);
        CP_COMMIT();
        if (t + 2 < NKIT) {
            int nb = abuf + 2; if (nb >= 3) nb -= 3;
            load_a(sb, t + 2, nb, tid, mbase);
        }
        CP_COMMIT();

        const uint32_t* As = sm + abuf * ASZW;
        const uint32_t* Bs = sm + B_OFF + (t & 1) * BSZW;

        #pragma unroll
        for (int s = 0; s < 4; s++) {             // 4 k16-steps
            uint2 aF[4][2];
            #pragma unroll
            for (int mt = 0; mt < 4; mt++) {
                const uint32_t* ap = As + (warp_m * 64 + mt * 16 + r) * ASTRIDE + s * 8 + 2 * c;
                aF[mt][0] = *(const uint2*)ap;
                aF[mt][1] = *(const uint2*)(ap + 8 * ASTRIDE);
            }
            uint2 bF[4];
            #pragma unroll
            for (int nt = 0; nt < 4; nt++) {
                const uint32_t* bp = Bs + (warp_n * 32 + nt * 8 + r) * BSTRIDE + s * 8 + 2 * c;
                bF[nt] = *(const uint2*)bp;
            }
            #pragma unroll
            for (int mt = 0; mt < 4; mt++)
                #pragma unroll
                for (int nt = 0; nt < 4; nt++)
                    mma_f16(&acc[(mt * 4 + nt) * 4],
                            aF[mt][0].x, aF[mt][1].x, aF[mt][0].y, aF[mt][1].y,
                            bF[nt].x, bF[nt].y);
        }

        abuf = abuf + 1; if (abuf == 3) abuf = 0;
    }

    // epilogue: + bias, write fp32 out
    #pragma unroll
    for (int mt = 0; mt < 4; mt++) {
        size_t gm = mbase + warp_m * 64 + mt * 16 + r;
        float* o0 = out + gm * FOUT;
        #pragma unroll
        for (int nt = 0; nt < 4; nt++) {
            int col = nbase + warp_n * 32 + nt * 8 + 2 * c;
            float b0 = __ldg(bias + col), b1 = __ldg(bias + col + 1);
            const float* a = &acc[(mt * 4 + nt) * 4];
            *(float2*)(o0 + col)            = make_float2(a[0] + b0, a[1] + b1);
            *(float2*)(o0 + 8 * FOUT + col) = make_float2(a[2] + b0, a[3] + b1);
        }
    }
}

// ---------------- launch ----------------
extern "C" void kernel_launch(void* const* d_in, const int* in_sizes, int n_in,
                              void* d_out, int out_size) {
    const float* x    = (const float*)d_in[0];   // [16384,17,256]
    const float* W    = (const float*)d_in[1];   // [3,256,256]
    const float* adj  = (const float*)d_in[2];   // [17,17]
    const float* bias = (const float*)d_in[3];   // [256]
    float* out = (float*)d_out;                  // [16384,17,256]

    cudaFuncSetAttribute(fused_kernel, cudaFuncAttributeMaxDynamicSharedMemorySize, SMEM_BYTES);

    prep_kernel<<<384, 256>>>(W);
    fused_kernel<<<NAGG + NGEMM, 256, SMEM_BYTES>>>(x, adj, bias, out);
}

// round 13
// speedup vs baseline: 1.2078x; 1.2078x over previous
#include <cuda_runtime.h>
#include <cuda_fp16.h>
#include <cstdint>
#include <cstddef>

// ---------------- problem constants ----------------
#define BATCH 16384
#define JNT   17
#define FIN   256
#define FOUT  256
#define MROWS (BATCH * JNT)          // 278528 = 2176 * 128
#define PROW  384                    // uint32 (fp16-pairs) per z row

// GEMM tiling: CTA 128x128, 8 warps of 64x32, BK=64; A 3-stage(48), B 2-stage(40)
#define BM 128
#define BN 128
#define NKIT 12
#define ASTRIDE 48                   // uint32 per A smem row (LDS.128 conflict-free)
#define BSTRIDE 40
#define ASZW (BM * ASTRIDE)          // 6144 uint32 per A stage
#define BSZW (BN * BSTRIDE)          // 5120 uint32 per B stage
#define B_OFF (3 * ASZW)             // 18432
#define SMEM_BYTES ((3 * ASZW + 2 * BSZW) * 4)   // 114688 -> exactly 2 CTAs/SM

// agg smem: 4 batches of x + adj
#define AGG_SMEM ((4 * JNT * FIN + JNT * JNT) * 4)   // 70788 bytes

// ---------------- device scratch ----------------
__device__ uint32_t g_z[(size_t)MROWS * PROW];       // z fp16 pairs (~428MB), S-layout
__device__ uint32_t g_wb[(size_t)NKIT * 256 * 32];   // Wcat prepacked fp16 (old layout)

// ---------------- helpers ----------------
__device__ __forceinline__ uint32_t smem_u32(const void* p) {
    uint32_t a;
    asm("{ .reg .u64 t; cvta.to.shared.u64 t, %1; cvt.u32.u64 %0, t; }" : "=r"(a) : "l"(p));
    return a;
}
__device__ __forceinline__ void cp16(uint32_t dst, const void* src) {
    asm volatile("cp.async.cg.shared.global [%0], [%1], 16;" :: "r"(dst), "l"(src));
}
#define CP_COMMIT() asm volatile("cp.async.commit_group;" ::: "memory")
#define CP_WAIT1()  asm volatile("cp.async.wait_group 1;" ::: "memory")

__device__ __forceinline__ void mma_f16(float* d, uint32_t a0, uint32_t a1,
                                        uint32_t a2, uint32_t a3,
                                        uint32_t b0, uint32_t b1) {
    asm volatile(
        "mma.sync.aligned.m16n8k16.row.col.f32.f16.f16.f32 "
        "{%0,%1,%2,%3}, {%4,%5,%6,%7}, {%8,%9}, {%0,%1,%2,%3};"
        : "+f"(d[0]), "+f"(d[1]), "+f"(d[2]), "+f"(d[3])
        : "r"(a0), "r"(a1), "r"(a2), "r"(a3), "r"(b0), "r"(b1));
}
__device__ __forceinline__ uint32_t pack2(float lo, float hi) {
    __half2 h = __floats2half2_rn(lo, hi);
    return *reinterpret_cast<uint32_t*>(&h);
}

// A (z) slot layout, per 32-pair iter chunk:
//   slot(S, c, shalf, half) = 16S + 4c + 2shalf + half, step s = 2S + shalf,
//   half 0 -> pair 8s+c (R0 side), half 1 -> pair 8s+c+4 (R2 side).
//   uint4 at 16S+4c = both k16-steps' fragment halves for thread column c.
// B keeps old layout: slot = s*8 + (q&3)*2 + (q>>2) within its 8-group.

// ---------------- kernel 1: aggregation -> z  (+ merged W prepack) ----------------
__global__ void __launch_bounds__(256) agg_kernel(const float* __restrict__ x,
                                                  const float* __restrict__ adj,
                                                  const float* __restrict__ W) {
    extern __shared__ float sdyn[];
    float* sx   = sdyn;                       // 4*17*256
    float* sadj = sdyn + 4 * JNT * FIN;       // 289
    const int tid = threadIdx.x;
    const int b0 = blockIdx.x * 4;

    if (blockIdx.x < 384) {                   // merged W prepack (OLD B layout)
        int idx = blockIdx.x * 256 + tid;
        int s = idx & 31;
        int n = (idx >> 5) & 255;
        int t = idx >> 13;
        int sp = s & 7;
        int q = (sp >> 1) + ((sp & 1) << 2);  // inverse interleave
        int P = t * 32 + (s >> 3) * 8 + q;
        int k0 = 2 * P;
        g_wb[idx] = pack2(W[k0 * FOUT + n], W[(k0 + 1) * FOUT + n]);
    }

    const float4* xs = (const float4*)(x + (size_t)b0 * JNT * FIN);
    float4* sd = (float4*)sx;
    #pragma unroll
    for (int t = tid; t < 4 * JNT * FIN / 4; t += 256) sd[t] = xs[t];
    for (int t = tid; t < JNT * JNT; t += 256) sadj[t] = adj[t];
    __syncthreads();

    const int sub = tid >> 6;
    const int u = tid & 63;
    const int G = u >> 2, m = u & 3;
    const int f0 = G * 16 + m * 2;
    const float* xb = sx + sub * JNT * FIN;

    float2 xlo[JNT], xhi[JNT];
    #pragma unroll
    for (int j = 0; j < JNT; j++) {
        xlo[j] = *(const float2*)(xb + j * FIN + f0);
        xhi[j] = *(const float2*)(xb + j * FIN + f0 + 8);
    }

    // NEW A slot: pairs (8G+m, 8G+m+4) -> adjacent slots
    const int slot = 16 * (G >> 1) + 4 * m + 2 * (G & 1);
    uint32_t* zr = g_z + (size_t)(b0 + sub) * JNT * PROW;

    #pragma unroll
    for (int i = 0; i < JNT; i++) {
        float ad = sadj[i * JNT + i];
        float2 d_lo = make_float2(ad * xlo[i].x, ad * xlo[i].y);
        float2 d_hi = make_float2(ad * xhi[i].x, ad * xhi[i].y);
        float2 s1l = make_float2(0.f, 0.f), s1h = make_float2(0.f, 0.f);
        float2 s2l = make_float2(0.f, 0.f), s2h = make_float2(0.f, 0.f);
        #pragma unroll
        for (int j = 0; j < JNT; j++) {
            float a = sadj[i * JNT + j];
            if (j > i) {
                s1l.x += a * xlo[j].x; s1l.y += a * xlo[j].y;
                s1h.x += a * xhi[j].x; s1h.y += a * xhi[j].y;
            }
            if (j < i) {
                s2l.x += a * xlo[j].x; s2l.y += a * xlo[j].y;
                s2h.x += a * xhi[j].x; s2h.y += a * xhi[j].y;
            }
        }
        uint32_t* zi = zr + i * PROW;
        *(uint2*)(zi + slot)       = make_uint2(pack2(d_lo.x, d_lo.y), pack2(d_hi.x, d_hi.y));
        *(uint2*)(zi + 128 + slot) = make_uint2(pack2(s1l.x, s1l.y), pack2(s1h.x, s1h.y));
        *(uint2*)(zi + 256 + slot) = make_uint2(pack2(s2l.x, s2l.y), pack2(s2h.x, s2h.y));
    }
}

// ---------------- kernel 2: GEMM  out = z @ Wcat + bias ----------------
__device__ __forceinline__ void load_a(uint32_t sb, int t, int s, int tid, size_t mbase) {
    const uint32_t* za = g_z + mbase * PROW + t * 32;
    uint32_t as = sb + (uint32_t)s * ASZW * 4;
    #pragma unroll
    for (int qq = 0; qq < 4; qq++) {
        int id = tid + qq * 256;                  // 1024 chunks
        int row = id >> 3, ck = id & 7;
        cp16(as + (row * ASTRIDE + ck * 4) * 4, za + (size_t)row * PROW + ck * 4);
    }
}
__device__ __forceinline__ void load_b(uint32_t sb, int t, int s, int tid, int nbase) {
    const uint32_t* wb = g_wb + ((size_t)t * 256 + nbase) * 32;
    uint32_t bs = sb + ((uint32_t)(B_OFF + s * BSZW)) * 4;
    #pragma unroll
    for (int qq = 0; qq < 4; qq++) {
        int id = tid + qq * 256;
        int row = id >> 3, ck = id & 7;
        cp16(bs + (row * BSTRIDE + ck * 4) * 4, wb + id * 4);
    }
}

__global__ void __launch_bounds__(256, 2) gemm_kernel(float* __restrict__ out,
                                                      const float* __restrict__ bias) {
    extern __shared__ uint32_t sm[];
    const uint32_t sb = smem_u32(sm);
    const int tid = threadIdx.x;
    const int wid = tid >> 5;
    const int lane = tid & 31;
    const int warp_m = wid & 1;      // 2 x 64 = 128 M
    const int warp_n = wid >> 1;     // 4 x 32 = 128 N
    const int r = lane >> 2;
    const int c = lane & 3;
    // N-half on blockIdx.x: CTAs sharing an M-tile are adjacent bids -> A hits L2
    const int nbase = blockIdx.x * BN;
    const size_t mbase = (size_t)blockIdx.y * BM;

    float acc[64];
    #pragma unroll
    for (int i = 0; i < 64; i++) acc[i] = 0.0f;

    // prologue: group {A0,B0}, group {A1}
    load_a(sb, 0, 0, tid, mbase);
    load_b(sb, 0, 0, tid, nbase);
    CP_COMMIT();
    load_a(sb, 1, 1, tid, mbase);
    CP_COMMIT();

    int abuf = 0;                                 // t % 3
    for (int t = 0; t < NKIT; t++) {
        CP_WAIT1();                               // A(t), B(t) landed
        __syncthreads();                          // visible; iter t-1 reads done

        if (t + 1 < NKIT) load_b(sb, t + 1, (t + 1) & 1, tid, nbase);
        CP_COMMIT();
        if (t + 2 < NKIT) {
            int nb = abuf + 2; if (nb >= 3) nb -= 3;
            load_a(sb, t + 2, nb, tid, mbase);
        }
        CP_COMMIT();

        const uint32_t* As = sm + abuf * ASZW;
        const uint32_t* Bs = sm + B_OFF + (t & 1) * BSZW;

        #pragma unroll
        for (int S = 0; S < 2; S++) {             // 2 super-steps x 2 k16-steps
            uint4 aLo[4], aHi[4];
            #pragma unroll
            for (int mt = 0; mt < 4; mt++) {
                const uint32_t* ap = As + (warp_m * 64 + mt * 16 + r) * ASTRIDE + S * 16 + 4 * c;
                aLo[mt] = *(const uint4*)ap;                   // steps 2S, 2S+1: R0/R2 row r
                aHi[mt] = *(const uint4*)(ap + 8 * ASTRIDE);   // row r+8: R1/R3
            }
            #pragma unroll
            for (int sh = 0; sh < 2; sh++) {
                const int s = 2 * S + sh;
                uint2 bF[4];
                #pragma unroll
                for (int nt = 0; nt < 4; nt++) {
                    const uint32_t* bp = Bs + (warp_n * 32 + nt * 8 + r) * BSTRIDE + s * 8 + 2 * c;
                    bF[nt] = *(const uint2*)bp;
                }
                #pragma unroll
                for (int mt = 0; mt < 4; mt++) {
                    const uint32_t a0 = sh ? aLo[mt].z : aLo[mt].x;
                    const uint32_t a1 = sh ? aHi[mt].z : aHi[mt].x;
                    const uint32_t a2 = sh ? aLo[mt].w : aLo[mt].y;
                    const uint32_t a3 = sh ? aHi[mt].w : aHi[mt].y;
                    #pragma unroll
                    for (int nt = 0; nt < 4; nt++)
                        mma_f16(&acc[(mt * 4 + nt) * 4], a0, a1, a2, a3,
                                bF[nt].x, bF[nt].y);
                }
            }
        }

        abuf = abuf + 1; if (abuf == 3) abuf = 0;
    }

    // epilogue: + bias, write fp32 out
    #pragma unroll
    for (int mt = 0; mt < 4; mt++) {
        size_t gm = mbase + warp_m * 64 + mt * 16 + r;
        float* o0 = out + gm * FOUT;
        #pragma unroll
        for (int nt = 0; nt < 4; nt++) {
            int col = nbase + warp_n * 32 + nt * 8 + 2 * c;
            float b0 = __ldg(bias + col), b1 = __ldg(bias + col + 1);
            const float* a = &acc[(mt * 4 + nt) * 4];
            *(float2*)(o0 + col)            = make_float2(a[0] + b0, a[1] + b1);
            *(float2*)(o0 + 8 * FOUT + col) = make_float2(a[2] + b0, a[3] + b1);
        }
    }
}

// ---------------- launch ----------------
extern "C" void kernel_launch(void* const* d_in, const int* in_sizes, int n_in,
                              void* d_out, int out_size) {
    const float* x    = (const float*)d_in[0];   // [16384,17,256]
    const float* W    = (const float*)d_in[1];   // [3,256,256]
    const float* adj  = (const float*)d_in[2];   // [17,17]
    const float* bias = (const float*)d_in[3];   // [256]
    float* out = (float*)d_out;                  // [16384,17,256]

    cudaFuncSetAttribute(agg_kernel, cudaFuncAttributeMaxDynamicSharedMemorySize, AGG_SMEM);
    cudaFuncSetAttribute(gemm_kernel, cudaFuncAttributeMaxDynamicSharedMemorySize, SMEM_BYTES);

    agg_kernel<<<BATCH / 4, 256, AGG_SMEM>>>(x, adj, W);
    dim3 grid(2, MROWS / BM);
    gemm_kernel<<<grid, 256, SMEM_BYTES>>>(out, bias);
}

// round 14
// speedup vs baseline: 1.3439x; 1.1127x over previous
#include <cuda_runtime.h>
#include <cuda_fp16.h>
#include <cstdint>
#include <cstddef>

// ---------------- problem constants ----------------
#define BATCH 16384
#define JNT   17
#define FIN   256
#define FOUT  256
#define MROWS (BATCH * JNT)          // 278528 = 2176 * 128
#define PROW  384                    // uint32 (fp16-pairs) per z row

// GEMM tiling: CTA 128x128, 8 warps of 64x32, BK=64; A 3-stage, B 2-stage; 2 CTAs/SM
#define BM 128
#define BN 128
#define NKIT 12
#define ASTRIDE 40
#define BSTRIDE 40
#define ASZW (BM * ASTRIDE)          // 5120 uint32 per A stage
#define BSZW (BN * BSTRIDE)          // 5120 uint32 per B stage
#define B_OFF (3 * ASZW)
#define SMEM_BYTES ((3 * ASZW + 2 * BSZW) * 4)   // 102400 -> 2 CTAs/SM

// agg smem: 4 batches of x + adj
#define AGG_SMEM ((4 * JNT * FIN + JNT * JNT) * 4)   // 70788 bytes

// ---------------- device scratch ----------------
__device__ uint32_t g_z[(size_t)MROWS * PROW];       // z fp16 pairs (~428MB)
__device__ uint32_t g_wb[(size_t)NKIT * 256 * 32];   // Wcat prepacked fp16

// ---------------- helpers ----------------
__device__ __forceinline__ uint32_t smem_u32(const void* p) {
    uint32_t a;
    asm("{ .reg .u64 t; cvta.to.shared.u64 t, %1; cvt.u32.u64 %0, t; }" : "=r"(a) : "l"(p));
    return a;
}
__device__ __forceinline__ void cp16(uint32_t dst, const void* src) {
    asm volatile("cp.async.cg.shared.global [%0], [%1], 16;" :: "r"(dst), "l"(src));
}
#define CP_COMMIT() asm volatile("cp.async.commit_group;" ::: "memory")
#define CP_WAIT1()  asm volatile("cp.async.wait_group 1;" ::: "memory")

__device__ __forceinline__ void mma_f16(float* d, uint32_t a0, uint32_t a1,
                                        uint32_t a2, uint32_t a3,
                                        uint32_t b0, uint32_t b1) {
    asm volatile(
        "mma.sync.aligned.m16n8k16.row.col.f32.f16.f16.f32 "
        "{%0,%1,%2,%3}, {%4,%5,%6,%7}, {%8,%9}, {%0,%1,%2,%3};"
        : "+f"(d[0]), "+f"(d[1]), "+f"(d[2]), "+f"(d[3])
        : "r"(a0), "r"(a1), "r"(a2), "r"(a3), "r"(b0), "r"(b1));
}
__device__ __forceinline__ uint32_t pack2(float lo, float hi) {
    __half2 h = __floats2half2_rn(lo, hi);
    return *reinterpret_cast<uint32_t*>(&h);
}

// pair-interleave: within each 8-pair group, slot (2m, 2m+1) holds pairs (m, m+4).

// ---------------- kernel 1: aggregation -> z  (+ merged W prepack) ----------------
__global__ void __launch_bounds__(256) agg_kernel(const float* __restrict__ x,
                                                  const float* __restrict__ adj,
                                                  const float* __restrict__ W) {
    extern __shared__ float sdyn[];
    float* sx   = sdyn;                       // 4*17*256
    float* sadj = sdyn + 4 * JNT * FIN;       // 289
    const int tid = threadIdx.x;
    const int b0 = blockIdx.x * 4;

    if (blockIdx.x < 384) {                   // merged W prepack
        int idx = blockIdx.x * 256 + tid;
        int s = idx & 31;
        int n = (idx >> 5) & 255;
        int t = idx >> 13;
        int sp = s & 7;
        int q = (sp >> 1) + ((sp & 1) << 2);  // inverse interleave
        int P = t * 32 + (s >> 3) * 8 + q;
        int k0 = 2 * P;
        g_wb[idx] = pack2(W[k0 * FOUT + n], W[(k0 + 1) * FOUT + n]);
    }

    const float4* xs = (const float4*)(x + (size_t)b0 * JNT * FIN);
    float4* sd = (float4*)sx;
    #pragma unroll
    for (int t = tid; t < 4 * JNT * FIN / 4; t += 256) sd[t] = xs[t];
    for (int t = tid; t < JNT * JNT; t += 256) sadj[t] = adj[t];
    __syncthreads();

    const int sub = tid >> 6;
    const int u = tid & 63;
    const int G = u >> 2, m = u & 3;
    const int f0 = G * 16 + m * 2;
    const float* xb = sx + sub * JNT * FIN;

    float2 xlo[JNT], xhi[JNT];
    #pragma unroll
    for (int j = 0; j < JNT; j++) {
        xlo[j] = *(const float2*)(xb + j * FIN + f0);
        xhi[j] = *(const float2*)(xb + j * FIN + f0 + 8);
    }

    const int slot = G * 8 + 2 * m;           // even -> 8B-aligned uint2
    uint32_t* zr = g_z + (size_t)(b0 + sub) * JNT * PROW;

    #pragma unroll
    for (int i = 0; i < JNT; i++) {
        float ad = sadj[i * JNT + i];
        float2 d_lo = make_float2(ad * xlo[i].x, ad * xlo[i].y);
        float2 d_hi = make_float2(ad * xhi[i].x, ad * xhi[i].y);
        float2 s1l = make_float2(0.f, 0.f), s1h = make_float2(0.f, 0.f);
        float2 s2l = make_float2(0.f, 0.f), s2h = make_float2(0.f, 0.f);
        #pragma unroll
        for (int j = 0; j < JNT; j++) {
            float a = sadj[i * JNT + j];
            if (j > i) {
                s1l.x += a * xlo[j].x; s1l.y += a * xlo[j].y;
                s1h.x += a * xhi[j].x; s1h.y += a * xhi[j].y;
            }
            if (j < i) {
                s2l.x += a * xlo[j].x; s2l.y += a * xlo[j].y;
                s2h.x += a * xhi[j].x; s2h.y += a * xhi[j].y;
            }
        }
        uint32_t* zi = zr + i * PROW;
        *(uint2*)(zi + slot)       = make_uint2(pack2(d_lo.x, d_lo.y), pack2(d_hi.x, d_hi.y));
        *(uint2*)(zi + 128 + slot) = make_uint2(pack2(s1l.x, s1l.y), pack2(s1h.x, s1h.y));
        *(uint2*)(zi + 256 + slot) = make_uint2(pack2(s2l.x, s2l.y), pack2(s2h.x, s2h.y));
    }
}

// ---------------- kernel 2: GEMM  out = z @ Wcat + bias ----------------
__device__ __forceinline__ void load_a(uint32_t sb, int t, int s, int tid, size_t mbase) {
    const uint32_t* za = g_z + mbase * PROW + t * 32;
    uint32_t as = sb + (uint32_t)s * ASZW * 4;
    #pragma unroll
    for (int qq = 0; qq < 4; qq++) {
        int id = tid + qq * 256;                  // 1024 chunks
        int row = id >> 3, ck = id & 7;
        cp16(as + (row * ASTRIDE + ck * 4) * 4, za + (size_t)row * PROW + ck * 4);
    }
}
__device__ __forceinline__ void load_b(uint32_t sb, int t, int s, int tid, int nbase) {
    const uint32_t* wb = g_wb + ((size_t)t * 256 + nbase) * 32;
    uint32_t bs = sb + ((uint32_t)(B_OFF + s * BSZW)) * 4;
    #pragma unroll
    for (int qq = 0; qq < 4; qq++) {
        int id = tid + qq * 256;
        int row = id >> 3, ck = id & 7;
        cp16(bs + (row * BSTRIDE + ck * 4) * 4, wb + id * 4);
    }
}

__global__ void __launch_bounds__(256, 2) gemm_kernel(float* __restrict__ out,
                                                      const float* __restrict__ bias) {
    extern __shared__ uint32_t sm[];
    const uint32_t sb = smem_u32(sm);
    const int tid = threadIdx.x;
    const int wid = tid >> 5;
    const int lane = tid & 31;
    const int warp_m = wid & 1;      // 2 x 64 = 128 M
    const int warp_n = wid >> 1;     // 4 x 32 = 128 N
    const int r = lane >> 2;
    const int c = lane & 3;
    // N-half on blockIdx.x: CTAs sharing an M-tile are adjacent bids -> A hits L2
    const int nbase = blockIdx.x * BN;
    const size_t mbase = (size_t)blockIdx.y * BM;

    float acc[64];
    #pragma unroll
    for (int i = 0; i < 64; i++) acc[i] = 0.0f;

    // prologue: group {A0,B0}, group {A1}
    load_a(sb, 0, 0, tid, mbase);
    load_b(sb, 0, 0, tid, nbase);
    CP_COMMIT();
    load_a(sb, 1, 1, tid, mbase);
    CP_COMMIT();

    int abuf = 0;                                 // t % 3
    for (int t = 0; t < NKIT; t++) {
        CP_WAIT1();                               // A(t), B(t) landed (<=1 group pending)
        __syncthreads();                          // visible to all; iter t-1 reads done

        // single-barrier loop: prefetch AFTER the sync.
        // B(t+1) -> buffer last read at iter t-1 (safe); A(t+2) -> same argument.
        if (t + 1 < NKIT) load_b(sb, t + 1, (t + 1) & 1, tid, nbase);
        CP_COMMIT();
        if (t + 2 < NKIT) {
            int nb = abuf + 2; if (nb >= 3) nb -= 3;
            load_a(sb, t + 2, nb, tid, mbase);
        }
        CP_COMMIT();

        const uint32_t* As = sm + abuf * ASZW;
        const uint32_t* Bs = sm + B_OFF + (t & 1) * BSZW;

        #pragma unroll
        for (int s = 0; s < 4; s++) {             // 4 k16-steps
            uint2 aF[4][2];
            #pragma unroll
            for (int mt = 0; mt < 4; mt++) {
                const uint32_t* ap = As + (warp_m * 64 + mt * 16 + r) * ASTRIDE + s * 8 + 2 * c;
                aF[mt][0] = *(const uint2*)ap;                  // pairs c, c+4 of row r
                aF[mt][1] = *(const uint2*)(ap + 8 * ASTRIDE);  // row r+8
            }
            uint2 bF[4];
            #pragma unroll
            for (int nt = 0; nt < 4; nt++) {
                const uint32_t* bp = Bs + (warp_n * 32 + nt * 8 + r) * BSTRIDE + s * 8 + 2 * c;
                bF[nt] = *(const uint2*)bp;
            }
            #pragma unroll
            for (int mt = 0; mt < 4; mt++)
                #pragma unroll
                for (int nt = 0; nt < 4; nt++)
                    mma_f16(&acc[(mt * 4 + nt) * 4],
                            aF[mt][0].x, aF[mt][1].x, aF[mt][0].y, aF[mt][1].y,
                            bF[nt].x, bF[nt].y);
        }

        abuf = abuf + 1; if (abuf == 3) abuf = 0;
    }

    // epilogue: + bias, write fp32 out
    #pragma unroll
    for (int mt = 0; mt < 4; mt++) {
        size_t gm = mbase + warp_m * 64 + mt * 16 + r;
        float* o0 = out + gm * FOUT;
        #pragma unroll
        for (int nt = 0; nt < 4; nt++) {
            int col = nbase + warp_n * 32 + nt * 8 + 2 * c;
            float b0 = __ldg(bias + col), b1 = __ldg(bias + col + 1);
            const float* a = &acc[(mt * 4 + nt) * 4];
            *(float2*)(o0 + col)            = make_float2(a[0] + b0, a[1] + b1);
            *(float2*)(o0 + 8 * FOUT + col) = make_float2(a[2] + b0, a[3] + b1);
        }
    }
}

// ---------------- launch ----------------
extern "C" void kernel_launch(void* const* d_in, const int* in_sizes, int n_in,
                              void* d_out, int out_size) {
    const float* x    = (const float*)d_in[0];   // [16384,17,256]
    const float* W    = (const float*)d_in[1];   // [3,256,256]
    const float* adj  = (const float*)d_in[2];   // [17,17]
    const float* bias = (const float*)d_in[3];   // [256]
    float* out = (float*)d_out;                  // [16384,17,256]

    cudaFuncSetAttribute(agg_kernel, cudaFuncAttributeMaxDynamicSharedMemorySize, AGG_SMEM);
    cudaFuncSetAttribute(gemm_kernel, cudaFuncAttributeMaxDynamicSharedMemorySize, SMEM_BYTES);

    agg_kernel<<<BATCH / 4, 256, AGG_SMEM>>>(x, adj, W);
    dim3 grid(2, MROWS / BM);
    gemm_kernel<<<grid, 256, SMEM_BYTES>>>(out, bias);
}